// round 15
// baseline (speedup 1.0000x reference)
#include <cuda_runtime.h>

// ---------------------------------------------------------------------------
// EnergySRB R15 = R13 (best, 43.78us) + outer-loop unroll 2.
//  - CULL reverted -16 -> -17: the -16 experiment (R14) was time-NEUTRAL
//    while doubling error => surviving-lane work is not the binding
//    constraint. Restore the 12x error margin.
//  - #pragma unroll 2 on the grid-stride loop: halves loop-control issue per
//    pair, batches 6 streaming LDGs/iteration (MLP 3->6) against the
//    exposed-latency gap between 63% DRAM-active and wallclock.
//  - frozen: 2 launches (init: pack+cast+table/dvcut+out=energies; main:
//    smem bins -> direct atomicAdd into out), 2-bit packed species in smem,
//    8x-replicated coef table, clamped dvcut, grid 296 x 1024, 32 regs.
// ---------------------------------------------------------------------------

#define A2B_F 1.8897261258369282f
#define RC_F 9.826575854352027f          // 5.2 * A2B (bohr)
#define K1_F (A2B_F / RC_F)              // dv*K1 = d/rc
#define L2E_F 1.4426950408889634f
#define CULL_F (-17.0f)
#define DVCLAMP_F 5.19f                  // < 5.2 angstrom: guarantees u > 0

#define MAX_ATOKENS (512 * 1024)
#define MAX_MOLS (8192)
#define BIN_STRIDE 132                    // used by generic fallback only
#define BLOCK 1024
#define TAB_WORDS 272                     // 8 replicas * 17 float2 = 1088B

__device__ unsigned int g_packed[MAX_ATOKENS / 16];   // 2-bit species codes
__device__ float g_bins[MAX_MOLS * BIN_STRIDE];       // fallback path scratch
__device__ float2 g_tab[16];                          // (pre, dfac*A2B*L2E)
__device__ float g_dvcut;

__device__ __forceinline__ float rcp_approx(float x) {
    float y; asm("rcp.approx.f32 %0, %1;" : "=f"(y) : "f"(x)); return y;
}
__device__ __forceinline__ float ex2_approx(float x) {
    float y; asm("ex2.approx.f32 %0, %1;" : "=f"(y) : "f"(x)); return y;
}

// ---------------------------------------------------------------------------
// Init: pack species (shuffle combine), cast species into out (same int4
// load), table + dvcut via warp reduce, pre-load out energies (fast path)
// or zero g_bins (fallback path).
// ---------------------------------------------------------------------------
__global__ void init_kernel(const int* __restrict__ species,
                            const float* __restrict__ pre_tab,
                            const float* __restrict__ dfac_tab,
                            const float* __restrict__ energies,
                            float* __restrict__ out,
                            int n_sp, int n_mol, int ne2,
                            int do_pack, int do_cast,
                            int e_base, int direct_out) {
    int t = blockIdx.x * blockDim.x + threadIdx.x;
    if (do_pack) {
        int n4 = n_sp >> 2;
        int n4f = (n_sp >> 4) << 2;       // int4 groups forming full 16-atom words
        if (t < n4) {
            int4 v = ((const int4*)species)[t];
            if (do_cast) {
                ((float4*)out)[t] = make_float4((float)v.x, (float)v.y,
                                                (float)v.z, (float)v.w);
            }
            if (t < n4f) {
                unsigned int chunk =
                    ((unsigned)v.x & 3u)        | (((unsigned)v.y & 3u) << 2) |
                    (((unsigned)v.z & 3u) << 4) | (((unsigned)v.w & 3u) << 6);
                unsigned int sub = (unsigned)t & 3u;
                unsigned int w = chunk << (sub * 8u);
                unsigned int gbase = (unsigned)(threadIdx.x & 31) & ~3u;
                unsigned int mask = 0xFu << gbase;
                w |= __shfl_xor_sync(mask, w, 1);
                w |= __shfl_xor_sync(mask, w, 2);
                if (sub == 0) g_packed[t >> 2] = w;
            }
        }
        if (t == n4 && (n_sp & 15)) {     // partial last packed word
            int wi = n_sp >> 4;
            unsigned int w = 0;
            int base = wi << 4;
            for (int j = 0; j < 16; j++) {
                int a = base + j;
                unsigned int v = (a < n_sp) ? ((unsigned int)species[a] & 3u) : 0u;
                w |= v << (2 * j);
            }
            g_packed[wi] = w;
        }
        if (do_cast && t < (n_sp & 3)) {  // cast remainder
            int a = (n_sp & ~3) + t;
            out[a] = (float)species[a];
        }
        // table + dvcut: lanes 0-15 of block 0, parallel loads + shfl reduce
        if (blockIdx.x == 0 && threadIdx.x < 16) {
            int lane = threadIdx.x;
            float c = -1e30f;
            if (lane < ne2) {
                float d = dfac_tab[lane] * A2B_F * L2E_F;
                g_tab[lane] = make_float2(pre_tab[lane], d);
                c = d;
            }
            #pragma unroll
            for (int off = 8; off; off >>= 1)
                c = fmaxf(c, __shfl_xor_sync(0xFFFFu, c, off));
            if (lane == 0) {
                float cut = (c < 0.0f) ? (CULL_F / c) : 1e30f;
                if (cut > DVCLAMP_F) cut = DVCLAMP_F;   // survivors => u > 0
                g_dvcut = cut;
            }
        }
    }
    if (t < n_mol) {
        if (direct_out) out[e_base + t] = energies[t];   // fast path
        else            g_bins[t * BIN_STRIDE] = 0.0f;   // fallback scratch
    }
}

// ---------------------------------------------------------------------------
// Main kernel: smem bins, flush straight into out[e_base..].
// smem: coef table replicas | bins | packed species.
// ---------------------------------------------------------------------------
__global__ void __launch_bounds__(BLOCK, 2)
srb_main_out(const int* __restrict__ idx0, const int* __restrict__ idx1,
             const float* __restrict__ dist, float* __restrict__ out,
             int nv, int na_shift, int nwords,
             int n_mol, int n_mol_pad, int e_base)
{
    extern __shared__ unsigned int s_mem[];
    float2* s_tab = (float2*)s_mem;                // 8 replicas, stride 17
    float* s_bins = (float*)(s_mem + TAB_WORDS);
    unsigned int* s_pk = s_mem + TAB_WORDS + n_mol_pad;

    if (threadIdx.x < 128) {
        int rep = threadIdx.x >> 4;
        int e = threadIdx.x & 15;
        s_tab[rep * 17 + e] = g_tab[e];
    }
    for (int j = threadIdx.x; j < n_mol; j += BLOCK)
        s_bins[j] = 0.0f;
    {
        const int4* __restrict__ src = (const int4*)g_packed;
        int4* dst = (int4*)s_pk;
        int nv4 = nwords >> 2;
        for (int j = threadIdx.x; j < nv4; j += BLOCK)
            dst[j] = src[j];
    }
    float dvcut = g_dvcut;
    int rbase = (threadIdx.x & 7) * 17;            // per-lane table replica
    __syncthreads();

    int tid = blockIdx.x * BLOCK + threadIdx.x;
    int stride = gridDim.x * BLOCK;

    const int4* __restrict__ p0 = (const int4*)idx0;
    const int4* __restrict__ p1 = (const int4*)idx1;
    const float4* __restrict__ pd = (const float4*)dist;

    #pragma unroll 2
    for (int i = tid; i < nv; i += stride) {
        int4 a = __ldcs(p0 + i);
        int4 b = __ldcs(p1 + i);
        float4 dd = __ldcs(pd + i);

        int ia[4] = {a.x, a.y, a.z, a.w};
        int ib[4] = {b.x, b.y, b.z, b.w};
        float dv[4] = {dd.x, dd.y, dd.z, dd.w};

        #pragma unroll
        for (int j = 0; j < 4; j++) {
            float dvj = dv[j];
            if (dvj < dvcut) {                     // safe cull; implies u > 0
                int i0 = ia[j], i1 = ib[j];
                unsigned int w0 = s_pk[i0 >> 4];
                unsigned int w1 = s_pk[i1 >> 4];
                int s0 = (int)((w0 >> ((i0 & 15) << 1)) & 3u);
                int s1 = (int)((w1 >> ((i1 & 15) << 1)) & 3u);
                float2 c = s_tab[rbase + ((s0 << 2) | s1)];

                float t = dvj * K1_F;
                float u = fmaf(-t, t, 1.0f);       // 1 - (d/rc)^2, > 0 here
                float r = rcp_approx(u);
                float arg = fmaf(c.y, dvj, fmaf(-L2E_F, r, L2E_F));

                if (arg > CULL_F) {
                    float srb = c.x * ex2_approx(arg);
                    int mol = i0 >> na_shift;
                    atomicAdd(&s_bins[mol], srb);  // smem RED (spread banks)
                }
            }
        }
    }

    // flush per-CTA bins straight into the output (coalesced REDG burst)
    __syncthreads();
    for (int j = threadIdx.x; j < n_mol; j += BLOCK) {
        float v = s_bins[j];
        if (v != 0.0f)
            atomicAdd(&out[e_base + j], v);
    }
}

// tail pairs [p_begin, P) scalar (exact, no cull) -> direct to out
__global__ void srb_tail(const int* __restrict__ idx0, const int* __restrict__ idx1,
                         const float* __restrict__ dist, float* __restrict__ out,
                         int p_begin, int P, int na_shift, int e_base)
{
    int p = p_begin + blockIdx.x * blockDim.x + threadIdx.x;
    if (p < P) {
        int i0 = idx0[p], i1 = idx1[p];
        float t = dist[p] * K1_F;
        float u = fmaf(-t, t, 1.0f);
        if (u > 0.0f) {
            unsigned int w0 = g_packed[i0 >> 4];
            unsigned int w1 = g_packed[i1 >> 4];
            int s0 = (int)((w0 >> ((i0 & 15) << 1)) & 3u);
            int s1 = (int)((w1 >> ((i1 & 15) << 1)) & 3u);
            float2 c = g_tab[(s0 << 2) + s1];
            float r = rcp_approx(u);
            float arg = fmaf(c.y, dist[p], fmaf(-L2E_F, r, L2E_F));
            float srb = c.x * ex2_approx(arg);
            int mol = i0 >> na_shift;
            atomicAdd(&out[e_base + mol], srb);
        }
    }
}

// ---------------------------------------------------------------------------
// Generic fallback (any n_elem / non-pow2 n_atoms / large n_sp) -> g_bins
// ---------------------------------------------------------------------------
__global__ void __launch_bounds__(256)
srb_kernel_generic(const int* __restrict__ idx0, const int* __restrict__ idx1,
                   const float* __restrict__ dist, const int* __restrict__ species,
                   const float* __restrict__ pre_tab, const float* __restrict__ dfac_tab,
                   int P, int n_elem, int na_shift, int n_atoms)
{
    __shared__ float2 s_tab[64];
    int ne2 = n_elem * n_elem;
    for (int j = threadIdx.x; j < ne2; j += blockDim.x)
        s_tab[j] = make_float2(pre_tab[j], dfac_tab[j] * A2B_F * L2E_F);
    __syncthreads();

    int tid = blockIdx.x * blockDim.x + threadIdx.x;
    int stride = gridDim.x * blockDim.x;
    for (int p = tid; p < P; p += stride) {
        int i0 = idx0[p], i1 = idx1[p];
        float t = dist[p] * K1_F;
        float u = fmaf(-t, t, 1.0f);
        if (u > 0.0f) {
            int s0 = species[i0];
            int s1 = species[i1];
            float2 c = s_tab[s0 * n_elem + s1];
            float r = rcp_approx(u);
            float arg = fmaf(c.y, dist[p], fmaf(-L2E_F, r, L2E_F));
            float srb = c.x * ex2_approx(arg);
            int mol = (na_shift >= 0) ? (i0 >> na_shift) : (i0 / n_atoms);
            atomicAdd(&g_bins[mol * BIN_STRIDE], srb);
        }
    }
}

// fallback finalize (generic path only)
__global__ void finalize_kernel(const float* __restrict__ energies,
                                const int* __restrict__ species,
                                float* __restrict__ out,
                                int n_mol, int n_sp, int mode) {
    int t = blockIdx.x * blockDim.x + threadIdx.x;
    if (mode == 1) {
        int n4 = n_sp >> 2;
        if (t < n4) {
            int4 s = ((const int4*)species)[t];
            ((float4*)out)[t] = make_float4((float)s.x, (float)s.y, (float)s.z, (float)s.w);
        } else if (t < n4 + n_mol) {
            int m = t - n4;
            out[n_sp + m] = energies[m] + g_bins[m * BIN_STRIDE];
        }
        int rem = n_sp & 3;
        if (t < rem) {
            int a = (n_sp & ~3) + t;
            out[a] = (float)species[a];
        }
    } else if (mode == 2) {
        if (t < n_sp) out[t] = (float)species[t];
    } else {
        if (t < n_mol) out[t] = energies[t] + g_bins[t * BIN_STRIDE];
    }
}

// ---------------------------------------------------------------------------
extern "C" void kernel_launch(void* const* d_in, const int* in_sizes, int n_in,
                              void* d_out, int out_size) {
    const int*   species  = (const int*)d_in[0];
    const float* energies = (const float*)d_in[1];
    const int*   ai12     = (const int*)d_in[2];
    const float* dist     = (const float*)d_in[3];
    const float* pre_tab  = (const float*)d_in[4];
    const float* dfac_tab = (const float*)d_in[5];

    int n_sp  = in_sizes[0];
    int n_mol = in_sizes[1];
    int P     = in_sizes[3];
    int n_atoms = (n_mol > 0) ? (n_sp / n_mol) : 1;
    if (n_atoms < 1) n_atoms = 1;

    int n_elem = 1;
    while (n_elem * n_elem < in_sizes[4]) n_elem++;

    int na_shift = -1;
    if ((n_atoms & (n_atoms - 1)) == 0) {
        int s = 0; int v = n_atoms;
        while (v > 1) { v >>= 1; s++; }
        na_shift = s;
    }

    bool packed = (n_elem == 4) && (n_sp <= MAX_ATOKENS) && (na_shift >= 0);

    int nwords = (n_sp + 15) >> 4;
    int nwords_pad = (nwords + 3) & ~3;
    int n_mol_pad = (n_mol + 3) & ~3;

    float* out = (float*)d_out;
    int mode;
    if (out_size == n_mol) mode = 0;
    else if (out_size == n_sp + n_mol) mode = 1;
    else if (out_size == n_sp) mode = 2;
    else mode = 0;

    size_t smem_sbin = (size_t)(TAB_WORDS + n_mol_pad + nwords_pad) * 4;
    bool fast = packed && (n_mol <= MAX_MOLS) && (2 * smem_sbin <= 220 * 1024);

    int do_cast = (packed && (mode == 1 || mode == 2)) ? 1 : 0;
    int e_base = (mode == 1) ? n_sp : 0;

    long long init_n = n_mol;
    if (packed) {
        long long pack_n = (long long)(n_sp >> 2) + 1;
        if (pack_n > init_n) init_n = pack_n;
    }
    if (init_n < 16) init_n = 16;
    int init_grid = (int)((init_n + 255) / 256);
    init_kernel<<<init_grid, 256>>>(species, pre_tab, dfac_tab, energies, out,
                                    n_sp, n_mol, n_elem * n_elem,
                                    packed ? 1 : 0, do_cast, e_base,
                                    fast ? 1 : 0);

    const int* idx0 = ai12;
    const int* idx1 = ai12 + P;

    if (fast) {
        if (mode != 2) {
            (void)cudaFuncSetAttribute(srb_main_out,
                                       cudaFuncAttributeMaxDynamicSharedMemorySize,
                                       (int)smem_sbin);
            int nv = P >> 2;
            int grid = 148 * 2;              // proven config
            long long want = ((long long)nv + BLOCK - 1) / BLOCK;
            if (want < grid) grid = (int)(want > 0 ? want : 1);
            if (grid < 1) grid = 1;
            srb_main_out<<<grid, BLOCK, smem_sbin>>>(idx0, idx1, dist, out,
                                                     nv, na_shift, nwords_pad,
                                                     n_mol, n_mol_pad, e_base);
            int rem = P & 3;
            if (rem)
                srb_tail<<<1, 32>>>(idx0, idx1, dist, out,
                                    P - rem, P, na_shift, e_base);
        }
        // mode==2: species cast written by init; no energy output region.
    } else {
        long long want = ((long long)P + 255) / 256;
        int grid = (want > 4736) ? 4736 : (int)(want > 0 ? want : 1);
        srb_kernel_generic<<<grid, 256>>>(idx0, idx1, dist, species,
                                          pre_tab, dfac_tab,
                                          P, n_elem, na_shift, n_atoms);
        long long fin_threads = (mode == 1) ? ((long long)(n_sp >> 2) + n_mol + 4)
                              : ((mode == 2) ? n_sp : n_mol);
        int fin_grid = (int)((fin_threads + 255) / 256);
        if (fin_grid < 1) fin_grid = 1;
        finalize_kernel<<<fin_grid, 256>>>(energies, species, out,
                                           n_mol, n_sp, mode);
    }
}

// round 16
// speedup vs baseline: 1.5636x; 1.5636x over previous
#include <cuda_runtime.h>

// ---------------------------------------------------------------------------
// EnergySRB R16 = R13 exactly (validated best: 43.78us, rel_err 7.9e-5).
//  R15's unroll-2 experiment regressed 43.8 -> 68.1us: at the 32-reg cap the
//  doubled loop body spilled/serialized the streaming loads (DRAM 63->40%,
//  L1 73->78%). Reverted. R14's CULL -16 was time-neutral at 2x the error:
//  kept at -17. Final configuration:
//  - 2 launches: init (pack species 2-bit + cast-to-float + coef table +
//    dvcut warp-reduce + out=energies), main (smem bins -> direct atomicAdd
//    into out).
//  - hot loop: vec4 streaming __ldcs, distance pre-cull (dvcut clamped so
//    survivors are inside the cutoff -> no u>0 test), packed species LDS,
//    8x-replicated stride-17 coef table, rcp/ex2 approx, exp2-arg cull -17,
//    smem atomics.
//  - grid 296 x 1024, 32 regs, ~100% occupancy.
// ---------------------------------------------------------------------------

#define A2B_F 1.8897261258369282f
#define RC_F 9.826575854352027f          // 5.2 * A2B (bohr)
#define K1_F (A2B_F / RC_F)              // dv*K1 = d/rc
#define L2E_F 1.4426950408889634f
#define CULL_F (-17.0f)
#define DVCLAMP_F 5.19f                  // < 5.2 angstrom: guarantees u > 0

#define MAX_ATOKENS (512 * 1024)
#define MAX_MOLS (8192)
#define BIN_STRIDE 132                    // used by generic fallback only
#define BLOCK 1024
#define TAB_WORDS 272                     // 8 replicas * 17 float2 = 1088B

__device__ unsigned int g_packed[MAX_ATOKENS / 16];   // 2-bit species codes
__device__ float g_bins[MAX_MOLS * BIN_STRIDE];       // fallback path scratch
__device__ float2 g_tab[16];                          // (pre, dfac*A2B*L2E)
__device__ float g_dvcut;

__device__ __forceinline__ float rcp_approx(float x) {
    float y; asm("rcp.approx.f32 %0, %1;" : "=f"(y) : "f"(x)); return y;
}
__device__ __forceinline__ float ex2_approx(float x) {
    float y; asm("ex2.approx.f32 %0, %1;" : "=f"(y) : "f"(x)); return y;
}

// ---------------------------------------------------------------------------
// Init: pack species (shuffle combine), cast species into out (same int4
// load), table + dvcut via warp reduce, pre-load out energies (fast path)
// or zero g_bins (fallback path).
// ---------------------------------------------------------------------------
__global__ void init_kernel(const int* __restrict__ species,
                            const float* __restrict__ pre_tab,
                            const float* __restrict__ dfac_tab,
                            const float* __restrict__ energies,
                            float* __restrict__ out,
                            int n_sp, int n_mol, int ne2,
                            int do_pack, int do_cast,
                            int e_base, int direct_out) {
    int t = blockIdx.x * blockDim.x + threadIdx.x;
    if (do_pack) {
        int n4 = n_sp >> 2;
        int n4f = (n_sp >> 4) << 2;       // int4 groups forming full 16-atom words
        if (t < n4) {
            int4 v = ((const int4*)species)[t];
            if (do_cast) {
                ((float4*)out)[t] = make_float4((float)v.x, (float)v.y,
                                                (float)v.z, (float)v.w);
            }
            if (t < n4f) {
                unsigned int chunk =
                    ((unsigned)v.x & 3u)        | (((unsigned)v.y & 3u) << 2) |
                    (((unsigned)v.z & 3u) << 4) | (((unsigned)v.w & 3u) << 6);
                unsigned int sub = (unsigned)t & 3u;
                unsigned int w = chunk << (sub * 8u);
                unsigned int gbase = (unsigned)(threadIdx.x & 31) & ~3u;
                unsigned int mask = 0xFu << gbase;
                w |= __shfl_xor_sync(mask, w, 1);
                w |= __shfl_xor_sync(mask, w, 2);
                if (sub == 0) g_packed[t >> 2] = w;
            }
        }
        if (t == n4 && (n_sp & 15)) {     // partial last packed word
            int wi = n_sp >> 4;
            unsigned int w = 0;
            int base = wi << 4;
            for (int j = 0; j < 16; j++) {
                int a = base + j;
                unsigned int v = (a < n_sp) ? ((unsigned int)species[a] & 3u) : 0u;
                w |= v << (2 * j);
            }
            g_packed[wi] = w;
        }
        if (do_cast && t < (n_sp & 3)) {  // cast remainder
            int a = (n_sp & ~3) + t;
            out[a] = (float)species[a];
        }
        // table + dvcut: lanes 0-15 of block 0, parallel loads + shfl reduce
        if (blockIdx.x == 0 && threadIdx.x < 16) {
            int lane = threadIdx.x;
            float c = -1e30f;
            if (lane < ne2) {
                float d = dfac_tab[lane] * A2B_F * L2E_F;
                g_tab[lane] = make_float2(pre_tab[lane], d);
                c = d;
            }
            #pragma unroll
            for (int off = 8; off; off >>= 1)
                c = fmaxf(c, __shfl_xor_sync(0xFFFFu, c, off));
            if (lane == 0) {
                float cut = (c < 0.0f) ? (CULL_F / c) : 1e30f;
                if (cut > DVCLAMP_F) cut = DVCLAMP_F;   // survivors => u > 0
                g_dvcut = cut;
            }
        }
    }
    if (t < n_mol) {
        if (direct_out) out[e_base + t] = energies[t];   // fast path
        else            g_bins[t * BIN_STRIDE] = 0.0f;   // fallback scratch
    }
}

// ---------------------------------------------------------------------------
// Main kernel: smem bins, flush straight into out[e_base..].
// smem: coef table replicas | bins | packed species.
// ---------------------------------------------------------------------------
__global__ void __launch_bounds__(BLOCK, 2)
srb_main_out(const int* __restrict__ idx0, const int* __restrict__ idx1,
             const float* __restrict__ dist, float* __restrict__ out,
             int nv, int na_shift, int nwords,
             int n_mol, int n_mol_pad, int e_base)
{
    extern __shared__ unsigned int s_mem[];
    float2* s_tab = (float2*)s_mem;                // 8 replicas, stride 17
    float* s_bins = (float*)(s_mem + TAB_WORDS);
    unsigned int* s_pk = s_mem + TAB_WORDS + n_mol_pad;

    if (threadIdx.x < 128) {
        int rep = threadIdx.x >> 4;
        int e = threadIdx.x & 15;
        s_tab[rep * 17 + e] = g_tab[e];
    }
    for (int j = threadIdx.x; j < n_mol; j += BLOCK)
        s_bins[j] = 0.0f;
    {
        const int4* __restrict__ src = (const int4*)g_packed;
        int4* dst = (int4*)s_pk;
        int nv4 = nwords >> 2;
        for (int j = threadIdx.x; j < nv4; j += BLOCK)
            dst[j] = src[j];
    }
    float dvcut = g_dvcut;
    int rbase = (threadIdx.x & 7) * 17;            // per-lane table replica
    __syncthreads();

    int tid = blockIdx.x * BLOCK + threadIdx.x;
    int stride = gridDim.x * BLOCK;

    const int4* __restrict__ p0 = (const int4*)idx0;
    const int4* __restrict__ p1 = (const int4*)idx1;
    const float4* __restrict__ pd = (const float4*)dist;

    for (int i = tid; i < nv; i += stride) {
        int4 a = __ldcs(p0 + i);
        int4 b = __ldcs(p1 + i);
        float4 dd = __ldcs(pd + i);

        int ia[4] = {a.x, a.y, a.z, a.w};
        int ib[4] = {b.x, b.y, b.z, b.w};
        float dv[4] = {dd.x, dd.y, dd.z, dd.w};

        #pragma unroll
        for (int j = 0; j < 4; j++) {
            float dvj = dv[j];
            if (dvj < dvcut) {                     // safe cull; implies u > 0
                int i0 = ia[j], i1 = ib[j];
                unsigned int w0 = s_pk[i0 >> 4];
                unsigned int w1 = s_pk[i1 >> 4];
                int s0 = (int)((w0 >> ((i0 & 15) << 1)) & 3u);
                int s1 = (int)((w1 >> ((i1 & 15) << 1)) & 3u);
                float2 c = s_tab[rbase + ((s0 << 2) | s1)];

                float t = dvj * K1_F;
                float u = fmaf(-t, t, 1.0f);       // 1 - (d/rc)^2, > 0 here
                float r = rcp_approx(u);
                float arg = fmaf(c.y, dvj, fmaf(-L2E_F, r, L2E_F));

                if (arg > CULL_F) {
                    float srb = c.x * ex2_approx(arg);
                    int mol = i0 >> na_shift;
                    atomicAdd(&s_bins[mol], srb);  // smem RED (spread banks)
                }
            }
        }
    }

    // flush per-CTA bins straight into the output (coalesced REDG burst)
    __syncthreads();
    for (int j = threadIdx.x; j < n_mol; j += BLOCK) {
        float v = s_bins[j];
        if (v != 0.0f)
            atomicAdd(&out[e_base + j], v);
    }
}

// tail pairs [p_begin, P) scalar (exact, no cull) -> direct to out
__global__ void srb_tail(const int* __restrict__ idx0, const int* __restrict__ idx1,
                         const float* __restrict__ dist, float* __restrict__ out,
                         int p_begin, int P, int na_shift, int e_base)
{
    int p = p_begin + blockIdx.x * blockDim.x + threadIdx.x;
    if (p < P) {
        int i0 = idx0[p], i1 = idx1[p];
        float t = dist[p] * K1_F;
        float u = fmaf(-t, t, 1.0f);
        if (u > 0.0f) {
            unsigned int w0 = g_packed[i0 >> 4];
            unsigned int w1 = g_packed[i1 >> 4];
            int s0 = (int)((w0 >> ((i0 & 15) << 1)) & 3u);
            int s1 = (int)((w1 >> ((i1 & 15) << 1)) & 3u);
            float2 c = g_tab[(s0 << 2) + s1];
            float r = rcp_approx(u);
            float arg = fmaf(c.y, dist[p], fmaf(-L2E_F, r, L2E_F));
            float srb = c.x * ex2_approx(arg);
            int mol = i0 >> na_shift;
            atomicAdd(&out[e_base + mol], srb);
        }
    }
}

// ---------------------------------------------------------------------------
// Generic fallback (any n_elem / non-pow2 n_atoms / large n_sp) -> g_bins
// ---------------------------------------------------------------------------
__global__ void __launch_bounds__(256)
srb_kernel_generic(const int* __restrict__ idx0, const int* __restrict__ idx1,
                   const float* __restrict__ dist, const int* __restrict__ species,
                   const float* __restrict__ pre_tab, const float* __restrict__ dfac_tab,
                   int P, int n_elem, int na_shift, int n_atoms)
{
    __shared__ float2 s_tab[64];
    int ne2 = n_elem * n_elem;
    for (int j = threadIdx.x; j < ne2; j += blockDim.x)
        s_tab[j] = make_float2(pre_tab[j], dfac_tab[j] * A2B_F * L2E_F);
    __syncthreads();

    int tid = blockIdx.x * blockDim.x + threadIdx.x;
    int stride = gridDim.x * blockDim.x;
    for (int p = tid; p < P; p += stride) {
        int i0 = idx0[p], i1 = idx1[p];
        float t = dist[p] * K1_F;
        float u = fmaf(-t, t, 1.0f);
        if (u > 0.0f) {
            int s0 = species[i0];
            int s1 = species[i1];
            float2 c = s_tab[s0 * n_elem + s1];
            float r = rcp_approx(u);
            float arg = fmaf(c.y, dist[p], fmaf(-L2E_F, r, L2E_F));
            float srb = c.x * ex2_approx(arg);
            int mol = (na_shift >= 0) ? (i0 >> na_shift) : (i0 / n_atoms);
            atomicAdd(&g_bins[mol * BIN_STRIDE], srb);
        }
    }
}

// fallback finalize (generic path only)
__global__ void finalize_kernel(const float* __restrict__ energies,
                                const int* __restrict__ species,
                                float* __restrict__ out,
                                int n_mol, int n_sp, int mode) {
    int t = blockIdx.x * blockDim.x + threadIdx.x;
    if (mode == 1) {
        int n4 = n_sp >> 2;
        if (t < n4) {
            int4 s = ((const int4*)species)[t];
            ((float4*)out)[t] = make_float4((float)s.x, (float)s.y, (float)s.z, (float)s.w);
        } else if (t < n4 + n_mol) {
            int m = t - n4;
            out[n_sp + m] = energies[m] + g_bins[m * BIN_STRIDE];
        }
        int rem = n_sp & 3;
        if (t < rem) {
            int a = (n_sp & ~3) + t;
            out[a] = (float)species[a];
        }
    } else if (mode == 2) {
        if (t < n_sp) out[t] = (float)species[t];
    } else {
        if (t < n_mol) out[t] = energies[t] + g_bins[t * BIN_STRIDE];
    }
}

// ---------------------------------------------------------------------------
extern "C" void kernel_launch(void* const* d_in, const int* in_sizes, int n_in,
                              void* d_out, int out_size) {
    const int*   species  = (const int*)d_in[0];
    const float* energies = (const float*)d_in[1];
    const int*   ai12     = (const int*)d_in[2];
    const float* dist     = (const float*)d_in[3];
    const float* pre_tab  = (const float*)d_in[4];
    const float* dfac_tab = (const float*)d_in[5];

    int n_sp  = in_sizes[0];
    int n_mol = in_sizes[1];
    int P     = in_sizes[3];
    int n_atoms = (n_mol > 0) ? (n_sp / n_mol) : 1;
    if (n_atoms < 1) n_atoms = 1;

    int n_elem = 1;
    while (n_elem * n_elem < in_sizes[4]) n_elem++;

    int na_shift = -1;
    if ((n_atoms & (n_atoms - 1)) == 0) {
        int s = 0; int v = n_atoms;
        while (v > 1) { v >>= 1; s++; }
        na_shift = s;
    }

    bool packed = (n_elem == 4) && (n_sp <= MAX_ATOKENS) && (na_shift >= 0);

    int nwords = (n_sp + 15) >> 4;
    int nwords_pad = (nwords + 3) & ~3;
    int n_mol_pad = (n_mol + 3) & ~3;

    float* out = (float*)d_out;
    int mode;
    if (out_size == n_mol) mode = 0;
    else if (out_size == n_sp + n_mol) mode = 1;
    else if (out_size == n_sp) mode = 2;
    else mode = 0;

    size_t smem_sbin = (size_t)(TAB_WORDS + n_mol_pad + nwords_pad) * 4;
    bool fast = packed && (n_mol <= MAX_MOLS) && (2 * smem_sbin <= 220 * 1024);

    int do_cast = (packed && (mode == 1 || mode == 2)) ? 1 : 0;
    int e_base = (mode == 1) ? n_sp : 0;

    long long init_n = n_mol;
    if (packed) {
        long long pack_n = (long long)(n_sp >> 2) + 1;
        if (pack_n > init_n) init_n = pack_n;
    }
    if (init_n < 16) init_n = 16;
    int init_grid = (int)((init_n + 255) / 256);
    init_kernel<<<init_grid, 256>>>(species, pre_tab, dfac_tab, energies, out,
                                    n_sp, n_mol, n_elem * n_elem,
                                    packed ? 1 : 0, do_cast, e_base,
                                    fast ? 1 : 0);

    const int* idx0 = ai12;
    const int* idx1 = ai12 + P;

    if (fast) {
        if (mode != 2) {
            (void)cudaFuncSetAttribute(srb_main_out,
                                       cudaFuncAttributeMaxDynamicSharedMemorySize,
                                       (int)smem_sbin);
            int nv = P >> 2;
            int grid = 148 * 2;              // proven config
            long long want = ((long long)nv + BLOCK - 1) / BLOCK;
            if (want < grid) grid = (int)(want > 0 ? want : 1);
            if (grid < 1) grid = 1;
            srb_main_out<<<grid, BLOCK, smem_sbin>>>(idx0, idx1, dist, out,
                                                     nv, na_shift, nwords_pad,
                                                     n_mol, n_mol_pad, e_base);
            int rem = P & 3;
            if (rem)
                srb_tail<<<1, 32>>>(idx0, idx1, dist, out,
                                    P - rem, P, na_shift, e_base);
        }
        // mode==2: species cast written by init; no energy output region.
    } else {
        long long want = ((long long)P + 255) / 256;
        int grid = (want > 4736) ? 4736 : (int)(want > 0 ? want : 1);
        srb_kernel_generic<<<grid, 256>>>(idx0, idx1, dist, species,
                                          pre_tab, dfac_tab,
                                          P, n_elem, na_shift, n_atoms);
        long long fin_threads = (mode == 1) ? ((long long)(n_sp >> 2) + n_mol + 4)
                              : ((mode == 2) ? n_sp : n_mol);
        int fin_grid = (int)((fin_threads + 255) / 256);
        if (fin_grid < 1) fin_grid = 1;
        finalize_kernel<<<fin_grid, 256>>>(energies, species, out,
                                           n_mol, n_sp, mode);
    }
}

// round 17
// speedup vs baseline: 1.5647x; 1.0007x over previous
#include <cuda_runtime.h>

// ---------------------------------------------------------------------------
// EnergySRB FINAL (validated best: 43.55us, rel_err 7.9e-5, 2 runs).
//  Session: 131.8 -> 43.55us (3.03x). Structure:
//  - 2 graph nodes: init (2-bit species pack via shuffle-combine + float cast
//    reusing the same int4 load + coef table + dvcut warp-reduce +
//    out=energies preload), main (pair loop -> smem bins -> direct
//    atomicAdd into out).
//  - hot loop: vec4 streaming __ldcs (idx0/idx1/dist), distance pre-cull
//    with dvcut clamped under the cutoff radius (survivors => u>0, no test),
//    packed-species LDS, 8x-replicated stride-17 coef table (conflict ~1.3),
//    rcp/ex2 approx single-MUFU math, exp2-arg cull -17 (error x2.15/unit,
//    12x margin), smem atomics (spread banks).
//  - grid 296 x 1024, 32 regs, ~94% occupancy. Profile: DRAM 63% / L1 73% /
//    issue 70% - balanced latency-bound floor for random gather+scatter over
//    a 192MB stream. Rejected by experiment: CULL -16 (neutral, 2x error),
//    unroll 2 (reg-ceiling serialization, +24us), fused last-CTA epilogue
//    (serial tail, +9us). Rejected by analysis: predicated idx loads (0.5%
//    sector savings at random cull), predication-for-branches (raises L1tex),
//    wider species tables (smem capacity).
// ---------------------------------------------------------------------------

#define A2B_F 1.8897261258369282f
#define RC_F 9.826575854352027f          // 5.2 * A2B (bohr)
#define K1_F (A2B_F / RC_F)              // dv*K1 = d/rc
#define L2E_F 1.4426950408889634f
#define CULL_F (-17.0f)
#define DVCLAMP_F 5.19f                  // < 5.2 angstrom: guarantees u > 0

#define MAX_ATOKENS (512 * 1024)
#define MAX_MOLS (8192)
#define BIN_STRIDE 132                    // used by generic fallback only
#define BLOCK 1024
#define TAB_WORDS 272                     // 8 replicas * 17 float2 = 1088B

__device__ unsigned int g_packed[MAX_ATOKENS / 16];   // 2-bit species codes
__device__ float g_bins[MAX_MOLS * BIN_STRIDE];       // fallback path scratch
__device__ float2 g_tab[16];                          // (pre, dfac*A2B*L2E)
__device__ float g_dvcut;

__device__ __forceinline__ float rcp_approx(float x) {
    float y; asm("rcp.approx.f32 %0, %1;" : "=f"(y) : "f"(x)); return y;
}
__device__ __forceinline__ float ex2_approx(float x) {
    float y; asm("ex2.approx.f32 %0, %1;" : "=f"(y) : "f"(x)); return y;
}

// ---------------------------------------------------------------------------
// Init: pack species (shuffle combine), cast species into out (same int4
// load), table + dvcut via warp reduce, pre-load out energies (fast path)
// or zero g_bins (fallback path).
// ---------------------------------------------------------------------------
__global__ void init_kernel(const int* __restrict__ species,
                            const float* __restrict__ pre_tab,
                            const float* __restrict__ dfac_tab,
                            const float* __restrict__ energies,
                            float* __restrict__ out,
                            int n_sp, int n_mol, int ne2,
                            int do_pack, int do_cast,
                            int e_base, int direct_out) {
    int t = blockIdx.x * blockDim.x + threadIdx.x;
    if (do_pack) {
        int n4 = n_sp >> 2;
        int n4f = (n_sp >> 4) << 2;       // int4 groups forming full 16-atom words
        if (t < n4) {
            int4 v = ((const int4*)species)[t];
            if (do_cast) {
                ((float4*)out)[t] = make_float4((float)v.x, (float)v.y,
                                                (float)v.z, (float)v.w);
            }
            if (t < n4f) {
                unsigned int chunk =
                    ((unsigned)v.x & 3u)        | (((unsigned)v.y & 3u) << 2) |
                    (((unsigned)v.z & 3u) << 4) | (((unsigned)v.w & 3u) << 6);
                unsigned int sub = (unsigned)t & 3u;
                unsigned int w = chunk << (sub * 8u);
                unsigned int gbase = (unsigned)(threadIdx.x & 31) & ~3u;
                unsigned int mask = 0xFu << gbase;
                w |= __shfl_xor_sync(mask, w, 1);
                w |= __shfl_xor_sync(mask, w, 2);
                if (sub == 0) g_packed[t >> 2] = w;
            }
        }
        if (t == n4 && (n_sp & 15)) {     // partial last packed word
            int wi = n_sp >> 4;
            unsigned int w = 0;
            int base = wi << 4;
            for (int j = 0; j < 16; j++) {
                int a = base + j;
                unsigned int v = (a < n_sp) ? ((unsigned int)species[a] & 3u) : 0u;
                w |= v << (2 * j);
            }
            g_packed[wi] = w;
        }
        if (do_cast && t < (n_sp & 3)) {  // cast remainder
            int a = (n_sp & ~3) + t;
            out[a] = (float)species[a];
        }
        // table + dvcut: lanes 0-15 of block 0, parallel loads + shfl reduce
        if (blockIdx.x == 0 && threadIdx.x < 16) {
            int lane = threadIdx.x;
            float c = -1e30f;
            if (lane < ne2) {
                float d = dfac_tab[lane] * A2B_F * L2E_F;
                g_tab[lane] = make_float2(pre_tab[lane], d);
                c = d;
            }
            #pragma unroll
            for (int off = 8; off; off >>= 1)
                c = fmaxf(c, __shfl_xor_sync(0xFFFFu, c, off));
            if (lane == 0) {
                float cut = (c < 0.0f) ? (CULL_F / c) : 1e30f;
                if (cut > DVCLAMP_F) cut = DVCLAMP_F;   // survivors => u > 0
                g_dvcut = cut;
            }
        }
    }
    if (t < n_mol) {
        if (direct_out) out[e_base + t] = energies[t];   // fast path
        else            g_bins[t * BIN_STRIDE] = 0.0f;   // fallback scratch
    }
}

// ---------------------------------------------------------------------------
// Main kernel: smem bins, flush straight into out[e_base..].
// smem: coef table replicas | bins | packed species.
// ---------------------------------------------------------------------------
__global__ void __launch_bounds__(BLOCK, 2)
srb_main_out(const int* __restrict__ idx0, const int* __restrict__ idx1,
             const float* __restrict__ dist, float* __restrict__ out,
             int nv, int na_shift, int nwords,
             int n_mol, int n_mol_pad, int e_base)
{
    extern __shared__ unsigned int s_mem[];
    float2* s_tab = (float2*)s_mem;                // 8 replicas, stride 17
    float* s_bins = (float*)(s_mem + TAB_WORDS);
    unsigned int* s_pk = s_mem + TAB_WORDS + n_mol_pad;

    if (threadIdx.x < 128) {
        int rep = threadIdx.x >> 4;
        int e = threadIdx.x & 15;
        s_tab[rep * 17 + e] = g_tab[e];
    }
    for (int j = threadIdx.x; j < n_mol; j += BLOCK)
        s_bins[j] = 0.0f;
    {
        const int4* __restrict__ src = (const int4*)g_packed;
        int4* dst = (int4*)s_pk;
        int nv4 = nwords >> 2;
        for (int j = threadIdx.x; j < nv4; j += BLOCK)
            dst[j] = src[j];
    }
    float dvcut = g_dvcut;
    int rbase = (threadIdx.x & 7) * 17;            // per-lane table replica
    __syncthreads();

    int tid = blockIdx.x * BLOCK + threadIdx.x;
    int stride = gridDim.x * BLOCK;

    const int4* __restrict__ p0 = (const int4*)idx0;
    const int4* __restrict__ p1 = (const int4*)idx1;
    const float4* __restrict__ pd = (const float4*)dist;

    for (int i = tid; i < nv; i += stride) {
        int4 a = __ldcs(p0 + i);
        int4 b = __ldcs(p1 + i);
        float4 dd = __ldcs(pd + i);

        int ia[4] = {a.x, a.y, a.z, a.w};
        int ib[4] = {b.x, b.y, b.z, b.w};
        float dv[4] = {dd.x, dd.y, dd.z, dd.w};

        #pragma unroll
        for (int j = 0; j < 4; j++) {
            float dvj = dv[j];
            if (dvj < dvcut) {                     // safe cull; implies u > 0
                int i0 = ia[j], i1 = ib[j];
                unsigned int w0 = s_pk[i0 >> 4];
                unsigned int w1 = s_pk[i1 >> 4];
                int s0 = (int)((w0 >> ((i0 & 15) << 1)) & 3u);
                int s1 = (int)((w1 >> ((i1 & 15) << 1)) & 3u);
                float2 c = s_tab[rbase + ((s0 << 2) | s1)];

                float t = dvj * K1_F;
                float u = fmaf(-t, t, 1.0f);       // 1 - (d/rc)^2, > 0 here
                float r = rcp_approx(u);
                float arg = fmaf(c.y, dvj, fmaf(-L2E_F, r, L2E_F));

                if (arg > CULL_F) {
                    float srb = c.x * ex2_approx(arg);
                    int mol = i0 >> na_shift;
                    atomicAdd(&s_bins[mol], srb);  // smem RED (spread banks)
                }
            }
        }
    }

    // flush per-CTA bins straight into the output (coalesced REDG burst)
    __syncthreads();
    for (int j = threadIdx.x; j < n_mol; j += BLOCK) {
        float v = s_bins[j];
        if (v != 0.0f)
            atomicAdd(&out[e_base + j], v);
    }
}

// tail pairs [p_begin, P) scalar (exact, no cull) -> direct to out
__global__ void srb_tail(const int* __restrict__ idx0, const int* __restrict__ idx1,
                         const float* __restrict__ dist, float* __restrict__ out,
                         int p_begin, int P, int na_shift, int e_base)
{
    int p = p_begin + blockIdx.x * blockDim.x + threadIdx.x;
    if (p < P) {
        int i0 = idx0[p], i1 = idx1[p];
        float t = dist[p] * K1_F;
        float u = fmaf(-t, t, 1.0f);
        if (u > 0.0f) {
            unsigned int w0 = g_packed[i0 >> 4];
            unsigned int w1 = g_packed[i1 >> 4];
            int s0 = (int)((w0 >> ((i0 & 15) << 1)) & 3u);
            int s1 = (int)((w1 >> ((i1 & 15) << 1)) & 3u);
            float2 c = g_tab[(s0 << 2) + s1];
            float r = rcp_approx(u);
            float arg = fmaf(c.y, dist[p], fmaf(-L2E_F, r, L2E_F));
            float srb = c.x * ex2_approx(arg);
            int mol = i0 >> na_shift;
            atomicAdd(&out[e_base + mol], srb);
        }
    }
}

// ---------------------------------------------------------------------------
// Generic fallback (any n_elem / non-pow2 n_atoms / large n_sp) -> g_bins
// ---------------------------------------------------------------------------
__global__ void __launch_bounds__(256)
srb_kernel_generic(const int* __restrict__ idx0, const int* __restrict__ idx1,
                   const float* __restrict__ dist, const int* __restrict__ species,
                   const float* __restrict__ pre_tab, const float* __restrict__ dfac_tab,
                   int P, int n_elem, int na_shift, int n_atoms)
{
    __shared__ float2 s_tab[64];
    int ne2 = n_elem * n_elem;
    for (int j = threadIdx.x; j < ne2; j += blockDim.x)
        s_tab[j] = make_float2(pre_tab[j], dfac_tab[j] * A2B_F * L2E_F);
    __syncthreads();

    int tid = blockIdx.x * blockDim.x + threadIdx.x;
    int stride = gridDim.x * blockDim.x;
    for (int p = tid; p < P; p += stride) {
        int i0 = idx0[p], i1 = idx1[p];
        float t = dist[p] * K1_F;
        float u = fmaf(-t, t, 1.0f);
        if (u > 0.0f) {
            int s0 = species[i0];
            int s1 = species[i1];
            float2 c = s_tab[s0 * n_elem + s1];
            float r = rcp_approx(u);
            float arg = fmaf(c.y, dist[p], fmaf(-L2E_F, r, L2E_F));
            float srb = c.x * ex2_approx(arg);
            int mol = (na_shift >= 0) ? (i0 >> na_shift) : (i0 / n_atoms);
            atomicAdd(&g_bins[mol * BIN_STRIDE], srb);
        }
    }
}

// fallback finalize (generic path only)
__global__ void finalize_kernel(const float* __restrict__ energies,
                                const int* __restrict__ species,
                                float* __restrict__ out,
                                int n_mol, int n_sp, int mode) {
    int t = blockIdx.x * blockDim.x + threadIdx.x;
    if (mode == 1) {
        int n4 = n_sp >> 2;
        if (t < n4) {
            int4 s = ((const int4*)species)[t];
            ((float4*)out)[t] = make_float4((float)s.x, (float)s.y, (float)s.z, (float)s.w);
        } else if (t < n4 + n_mol) {
            int m = t - n4;
            out[n_sp + m] = energies[m] + g_bins[m * BIN_STRIDE];
        }
        int rem = n_sp & 3;
        if (t < rem) {
            int a = (n_sp & ~3) + t;
            out[a] = (float)species[a];
        }
    } else if (mode == 2) {
        if (t < n_sp) out[t] = (float)species[t];
    } else {
        if (t < n_mol) out[t] = energies[t] + g_bins[t * BIN_STRIDE];
    }
}

// ---------------------------------------------------------------------------
extern "C" void kernel_launch(void* const* d_in, const int* in_sizes, int n_in,
                              void* d_out, int out_size) {
    const int*   species  = (const int*)d_in[0];
    const float* energies = (const float*)d_in[1];
    const int*   ai12     = (const int*)d_in[2];
    const float* dist     = (const float*)d_in[3];
    const float* pre_tab  = (const float*)d_in[4];
    const float* dfac_tab = (const float*)d_in[5];

    int n_sp  = in_sizes[0];
    int n_mol = in_sizes[1];
    int P     = in_sizes[3];
    int n_atoms = (n_mol > 0) ? (n_sp / n_mol) : 1;
    if (n_atoms < 1) n_atoms = 1;

    int n_elem = 1;
    while (n_elem * n_elem < in_sizes[4]) n_elem++;

    int na_shift = -1;
    if ((n_atoms & (n_atoms - 1)) == 0) {
        int s = 0; int v = n_atoms;
        while (v > 1) { v >>= 1; s++; }
        na_shift = s;
    }

    bool packed = (n_elem == 4) && (n_sp <= MAX_ATOKENS) && (na_shift >= 0);

    int nwords = (n_sp + 15) >> 4;
    int nwords_pad = (nwords + 3) & ~3;
    int n_mol_pad = (n_mol + 3) & ~3;

    float* out = (float*)d_out;
    int mode;
    if (out_size == n_mol) mode = 0;
    else if (out_size == n_sp + n_mol) mode = 1;
    else if (out_size == n_sp) mode = 2;
    else mode = 0;

    size_t smem_sbin = (size_t)(TAB_WORDS + n_mol_pad + nwords_pad) * 4;
    bool fast = packed && (n_mol <= MAX_MOLS) && (2 * smem_sbin <= 220 * 1024);

    int do_cast = (packed && (mode == 1 || mode == 2)) ? 1 : 0;
    int e_base = (mode == 1) ? n_sp : 0;

    long long init_n = n_mol;
    if (packed) {
        long long pack_n = (long long)(n_sp >> 2) + 1;
        if (pack_n > init_n) init_n = pack_n;
    }
    if (init_n < 16) init_n = 16;
    int init_grid = (int)((init_n + 255) / 256);
    init_kernel<<<init_grid, 256>>>(species, pre_tab, dfac_tab, energies, out,
                                    n_sp, n_mol, n_elem * n_elem,
                                    packed ? 1 : 0, do_cast, e_base,
                                    fast ? 1 : 0);

    const int* idx0 = ai12;
    const int* idx1 = ai12 + P;

    if (fast) {
        if (mode != 2) {
            (void)cudaFuncSetAttribute(srb_main_out,
                                       cudaFuncAttributeMaxDynamicSharedMemorySize,
                                       (int)smem_sbin);
            int nv = P >> 2;
            int grid = 148 * 2;              // proven config
            long long want = ((long long)nv + BLOCK - 1) / BLOCK;
            if (want < grid) grid = (int)(want > 0 ? want : 1);
            if (grid < 1) grid = 1;
            srb_main_out<<<grid, BLOCK, smem_sbin>>>(idx0, idx1, dist, out,
                                                     nv, na_shift, nwords_pad,
                                                     n_mol, n_mol_pad, e_base);
            int rem = P & 3;
            if (rem)
                srb_tail<<<1, 32>>>(idx0, idx1, dist, out,
                                    P - rem, P, na_shift, e_base);
        }
        // mode==2: species cast written by init; no energy output region.
    } else {
        long long want = ((long long)P + 255) / 256;
        int grid = (want > 4736) ? 4736 : (int)(want > 0 ? want : 1);
        srb_kernel_generic<<<grid, 256>>>(idx0, idx1, dist, species,
                                          pre_tab, dfac_tab,
                                          P, n_elem, na_shift, n_atoms);
        long long fin_threads = (mode == 1) ? ((long long)(n_sp >> 2) + n_mol + 4)
                              : ((mode == 2) ? n_sp : n_mol);
        int fin_grid = (int)((fin_threads + 255) / 256);
        if (fin_grid < 1) fin_grid = 1;
        finalize_kernel<<<fin_grid, 256>>>(energies, species, out,
                                           n_mol, n_sp, mode);
    }
}